// round 1
// baseline (speedup 1.0000x reference)
#include <cuda_runtime.h>
#include <cstddef>

// Problem constants (shapes fixed by the dataset)
#define HD 128           // hidden size H
#define FM 160           // FDIM_MESS
#define KNB 6            // MAX_NB
#define M_MSG 150000
#define N_NODE 50000

// ---------------------------------------------------------------------------
// Scratch: one big __device__ array, sliced on the host via symbol address.
// Layout (floats):
//   0..8  : nine M*H buffers (Z1, H1, R1, h, HU, SumH, SumG, Zlin, Hlin)
//   then  : NEI (N*H), T (N*H)
// ---------------------------------------------------------------------------
#define MH ((size_t)M_MSG * HD)          // 19,200,000
#define NH ((size_t)N_NODE * HD)         // 6,400,000
__device__ __align__(256) float g_scratch[9 * 19200000ull + 2 * 6400000ull];

// ---------------------------------------------------------------------------
// Helpers
// ---------------------------------------------------------------------------
__device__ __forceinline__ float sigm(float x) { return 1.0f / (1.0f + __expf(-x)); }

// ---------------------------------------------------------------------------
// SGEMM: C[M,128] = A[M,K] @ W[K,128] (+bias) (+Cadd, relu, row0-mask)
// 128x128 block tile, BK=16, 256 threads, 8x8 per thread.
// flags: 1=add bias[col], 2=add Cadd[row,col], 4=relu, 8=zero global row 0
// ---------------------------------------------------------------------------
__global__ void __launch_bounds__(256) gemm128_kernel(
    const float* __restrict__ A, int lda, int M, int K,
    const float* __restrict__ W,
    const float* __restrict__ bias,
    const float* __restrict__ Cadd,
    float* __restrict__ C, int flags)
{
    __shared__ float As[16][132];   // [k][row], padded to dodge store conflicts
    __shared__ float Ws[16][128];   // [k][col]

    const int tid = threadIdx.x;
    const int tx = tid & 15;        // col tile   (8 cols each)
    const int ty = tid >> 4;        // row tile   (8 rows each)
    const int r0 = blockIdx.x * 128;

    float acc[8][8];
#pragma unroll
    for (int i = 0; i < 8; i++)
#pragma unroll
        for (int j = 0; j < 8; j++) acc[i][j] = 0.0f;

    const int c4   = tid & 3;       // which float4 along K for A load
    const int arow = tid >> 2;      // 0..63 (two passes: arow, arow+64)
    const int wkr  = tid >> 5;      // 0..7  (two passes: wkr, wkr+8)
    const int wc4  = tid & 31;      // float4 along col for W load

    for (int kt = 0; kt < K; kt += 16) {
        // ---- load A tile (128 rows x 16 k), transpose into As[k][row]
#pragma unroll
        for (int rr = 0; rr < 2; rr++) {
            int r = arow + rr * 64;
            int grow = r0 + r;
            float4 v = make_float4(0.f, 0.f, 0.f, 0.f);
            if (grow < M)
                v = *(const float4*)(A + (size_t)grow * lda + kt + c4 * 4);
            As[c4 * 4 + 0][r] = v.x;
            As[c4 * 4 + 1][r] = v.y;
            As[c4 * 4 + 2][r] = v.z;
            As[c4 * 4 + 3][r] = v.w;
        }
        // ---- load W tile (16 k x 128 cols)
#pragma unroll
        for (int rr = 0; rr < 2; rr++) {
            int kr = wkr + rr * 8;
            float4 v = *(const float4*)(W + (size_t)(kt + kr) * HD + wc4 * 4);
            *(float4*)(&Ws[kr][wc4 * 4]) = v;
        }
        __syncthreads();

#pragma unroll
        for (int k = 0; k < 16; k++) {
            float a[8], b[8];
            *(float4*)(a)     = *(const float4*)(&As[k][ty * 8]);
            *(float4*)(a + 4) = *(const float4*)(&As[k][ty * 8 + 4]);
            *(float4*)(b)     = *(const float4*)(&Ws[k][tx * 8]);
            *(float4*)(b + 4) = *(const float4*)(&Ws[k][tx * 8 + 4]);
#pragma unroll
            for (int i = 0; i < 8; i++)
#pragma unroll
                for (int j = 0; j < 8; j++)
                    acc[i][j] += a[i] * b[j];
        }
        __syncthreads();
    }

    float bcol[8];
#pragma unroll
    for (int j = 0; j < 8; j++)
        bcol[j] = (flags & 1) ? bias[tx * 8 + j] : 0.0f;

#pragma unroll
    for (int i = 0; i < 8; i++) {
        int grow = r0 + ty * 8 + i;
        if (grow >= M) break;
#pragma unroll
        for (int j = 0; j < 8; j++) {
            int col = tx * 8 + j;
            float v = acc[i][j] + bcol[j];
            if (flags & 2) v += Cadd[(size_t)grow * HD + col];
            if (flags & 4) v = fmaxf(v, 0.0f);
            if ((flags & 8) && grow == 0) v = 0.0f;
            C[(size_t)grow * HD + col] = v;
        }
    }
}

// ---------------------------------------------------------------------------
// init_h: h = sigmoid(Z1) * tanh(H1), row 0 zeroed. (depth-step 1 with h=0)
// One float4 per thread.
// ---------------------------------------------------------------------------
__global__ void init_h_kernel(int total4, const float* __restrict__ Z1,
                              const float* __restrict__ H1,
                              float* __restrict__ h)
{
    int i = blockIdx.x * blockDim.x + threadIdx.x;
    if (i >= total4) return;
    float4 z = ((const float4*)Z1)[i];
    float4 p = ((const float4*)H1)[i];
    float4 o;
    o.x = sigm(z.x) * tanhf(p.x);
    o.y = sigm(z.y) * tanhf(p.y);
    o.z = sigm(z.z) * tanhf(p.z);
    o.w = sigm(z.w) * tanhf(p.w);
    if (i < HD / 4) { o.x = o.y = o.z = o.w = 0.0f; }   // message row 0 mask
    ((float4*)h)[i] = o;
}

// ---------------------------------------------------------------------------
// msg_gather: one warp per message.
//   SumH[m] = sum_k h[b]
//   SumG[m] = sum_k sigmoid(R1[m] + HU[b]) * h[b]
// ---------------------------------------------------------------------------
__global__ void __launch_bounds__(256) msg_gather_kernel(
    const int* __restrict__ bgraph, int M,
    const float* __restrict__ h, const float* __restrict__ HU,
    const float* __restrict__ R1,
    float* __restrict__ SumH, float* __restrict__ SumG)
{
    int warp = (blockIdx.x * blockDim.x + threadIdx.x) >> 5;
    if (warp >= M) return;
    int lane = threadIdx.x & 31;
    int d = lane * 4;

    float4 r1 = *(const float4*)(R1 + (size_t)warp * HD + d);
    float4 sh = make_float4(0.f, 0.f, 0.f, 0.f);
    float4 sg = make_float4(0.f, 0.f, 0.f, 0.f);

#pragma unroll
    for (int k = 0; k < KNB; k++) {
        int b = __ldg(bgraph + (size_t)warp * KNB + k);
        float4 hv = *(const float4*)(h  + (size_t)b * HD + d);
        float4 hu = *(const float4*)(HU + (size_t)b * HD + d);
        sh.x += hv.x; sh.y += hv.y; sh.z += hv.z; sh.w += hv.w;
        sg.x += sigm(r1.x + hu.x) * hv.x;
        sg.y += sigm(r1.y + hu.y) * hv.y;
        sg.z += sigm(r1.z + hu.z) * hv.z;
        sg.w += sigm(r1.w + hu.w) * hv.w;
    }
    *(float4*)(SumH + (size_t)warp * HD + d) = sh;
    *(float4*)(SumG + (size_t)warp * HD + d) = sg;
}

// ---------------------------------------------------------------------------
// update_h: z = sigmoid(Z1+Zlin); pre = tanh(H1+Hlin);
//           h = ((1-z)*SumH + z*pre), row 0 zeroed.
// ---------------------------------------------------------------------------
__global__ void update_h_kernel(int total4,
                                const float* __restrict__ Z1,
                                const float* __restrict__ Zlin,
                                const float* __restrict__ H1,
                                const float* __restrict__ Hlin,
                                const float* __restrict__ SumH,
                                float* __restrict__ h)
{
    int i = blockIdx.x * blockDim.x + threadIdx.x;
    if (i >= total4) return;
    float4 z1 = ((const float4*)Z1)[i];
    float4 zl = ((const float4*)Zlin)[i];
    float4 h1 = ((const float4*)H1)[i];
    float4 hl = ((const float4*)Hlin)[i];
    float4 s  = ((const float4*)SumH)[i];
    float4 o;
    {
        float z = sigm(z1.x + zl.x); float p = tanhf(h1.x + hl.x);
        o.x = (1.0f - z) * s.x + z * p;
    }
    {
        float z = sigm(z1.y + zl.y); float p = tanhf(h1.y + hl.y);
        o.y = (1.0f - z) * s.y + z * p;
    }
    {
        float z = sigm(z1.z + zl.z); float p = tanhf(h1.z + hl.z);
        o.z = (1.0f - z) * s.z + z * p;
    }
    {
        float z = sigm(z1.w + zl.w); float p = tanhf(h1.w + hl.w);
        o.w = (1.0f - z) * s.w + z * p;
    }
    if (i < HD / 4) { o.x = o.y = o.z = o.w = 0.0f; }
    ((float4*)h)[i] = o;
}

// ---------------------------------------------------------------------------
// node_gather: one warp per node, NEI[n] = sum_k h[agraph[n][k]]
// ---------------------------------------------------------------------------
__global__ void __launch_bounds__(256) node_gather_kernel(
    const int* __restrict__ agraph, int N,
    const float* __restrict__ h, float* __restrict__ NEI)
{
    int warp = (blockIdx.x * blockDim.x + threadIdx.x) >> 5;
    if (warp >= N) return;
    int lane = threadIdx.x & 31;
    int d = lane * 4;
    float4 s = make_float4(0.f, 0.f, 0.f, 0.f);
#pragma unroll
    for (int k = 0; k < KNB; k++) {
        int b = __ldg(agraph + (size_t)warp * KNB + k);
        float4 hv = *(const float4*)(h + (size_t)b * HD + d);
        s.x += hv.x; s.y += hv.y; s.z += hv.z; s.w += hv.w;
    }
    *(float4*)(NEI + (size_t)warp * HD + d) = s;
}

// ---------------------------------------------------------------------------
// Host-side orchestration
// ---------------------------------------------------------------------------
extern "C" void kernel_launch(void* const* d_in, const int* in_sizes, int n_in,
                              void* d_out, int out_size)
{
    const float* fnode  = (const float*)d_in[0];
    const float* fmess  = (const float*)d_in[1];
    const int*   agraph = (const int*)  d_in[2];
    const int*   bgraph = (const int*)  d_in[3];
    const float* W_z_w  = (const float*)d_in[4];   // [160+128, 128]
    const float* W_z_b  = (const float*)d_in[5];
    const float* W_r_w  = (const float*)d_in[6];   // [160, 128]
    const float* U_r_w  = (const float*)d_in[7];   // [128, 128]
    const float* U_r_b  = (const float*)d_in[8];
    const float* W_h_w  = (const float*)d_in[9];   // [160+128, 128]
    const float* W_h_b  = (const float*)d_in[10];
    const float* W_o_w  = (const float*)d_in[11];  // [128+128, 128]
    const float* W_o_b  = (const float*)d_in[12];
    float* out = (float*)d_out;

    const int N = in_sizes[0] / HD;   // nodes
    const int M = in_sizes[1] / FM;   // messages

    float* S = nullptr;
    cudaGetSymbolAddress((void**)&S, g_scratch);

    float* Z1   = S + 0 * MH;
    float* H1   = S + 1 * MH;
    float* R1   = S + 2 * MH;
    float* h    = S + 3 * MH;
    float* HU   = S + 4 * MH;
    float* SumH = S + 5 * MH;
    float* SumG = S + 6 * MH;
    float* Zlin = S + 7 * MH;
    float* Hlin = S + 8 * MH;
    float* NEI  = S + 9 * MH;
    float* T    = S + 9 * MH + NH;

    const int gemmBlocksM = (M + 127) / 128;
    const int gemmBlocksN = (N + 127) / 128;
    const dim3 tb(256);

    const int total4M = (int)(MH / 4);
    const int ewBlocksM = (total4M + 255) / 256;
    const int gatherBlocksM = (M + 7) / 8;   // 8 warps/block
    const int gatherBlocksN = (N + 7) / 8;

    // ---- loop-invariant precompute
    // Z1 = fmess @ Wz[0:160] + bz
    gemm128_kernel<<<gemmBlocksM, tb>>>(fmess, FM, M, FM, W_z_w, W_z_b, nullptr, Z1, 1);
    // H1 = fmess @ Wh[0:160] + bh
    gemm128_kernel<<<gemmBlocksM, tb>>>(fmess, FM, M, FM, W_h_w, W_h_b, nullptr, H1, 1);
    // R1 = fmess @ Wr + Ur_b
    gemm128_kernel<<<gemmBlocksM, tb>>>(fmess, FM, M, FM, W_r_w, U_r_b, nullptr, R1, 1);

    // ---- depth step 1 (h = 0): pure elementwise
    init_h_kernel<<<ewBlocksM, tb>>>(total4M, Z1, H1, h);

    // ---- depth steps 2..5
    const float* Wz_h = W_z_w + (size_t)FM * HD;   // rows 160..287
    const float* Wh_h = W_h_w + (size_t)FM * HD;
    for (int it = 0; it < 4; it++) {
        // HU = h @ U_r
        gemm128_kernel<<<gemmBlocksM, tb>>>(h, HD, M, HD, U_r_w, nullptr, nullptr, HU, 0);
        // SumH, SumG
        msg_gather_kernel<<<gatherBlocksM, tb>>>(bgraph, M, h, HU, R1, SumH, SumG);
        // Zlin = SumH @ Wz_h ; Hlin = SumG @ Wh_h
        gemm128_kernel<<<gemmBlocksM, tb>>>(SumH, HD, M, HD, Wz_h, nullptr, nullptr, Zlin, 0);
        gemm128_kernel<<<gemmBlocksM, tb>>>(SumG, HD, M, HD, Wh_h, nullptr, nullptr, Hlin, 0);
        // h update
        update_h_kernel<<<ewBlocksM, tb>>>(total4M, Z1, Zlin, H1, Hlin, SumH, h);
    }

    // ---- readout
    node_gather_kernel<<<gatherBlocksN, tb>>>(agraph, N, h, NEI);
    // T = fnode @ Wo[0:128] + bo
    gemm128_kernel<<<gemmBlocksN, tb>>>(fnode, HD, N, HD, W_o_w, W_o_b, nullptr, T, 1);
    // out = relu(T + NEI @ Wo[128:256]) masked at node 0
    const float* Wo_h = W_o_w + (size_t)HD * HD;
    gemm128_kernel<<<gemmBlocksN, tb>>>(NEI, HD, N, HD, Wo_h, nullptr, T, out, 2 | 4 | 8);
}

// round 2
// speedup vs baseline: 1.2282x; 1.2282x over previous
#include <cuda_runtime.h>
#include <cstdint>
#include <cstddef>

// Problem constants (shapes fixed by the dataset)
#define HD 128           // hidden size H
#define FM 160           // FDIM_MESS
#define KNB 6            // MAX_NB
#define M_MSG 150000
#define N_NODE 50000

#define MH ((size_t)M_MSG * HD)          // 19,200,000
#define NH ((size_t)N_NODE * HD)         // 6,400,000
__device__ __align__(256) float g_scratch[9 * 19200000ull + 2 * 6400000ull];

__device__ __forceinline__ float sigm(float x) { return 1.0f / (1.0f + __expf(-x)); }

__device__ __forceinline__ uint32_t f2tf32(float v) {
    uint32_t r;
    asm("cvt.rna.tf32.f32 %0, %1;" : "=r"(r) : "f"(v));
    return r;
}

__device__ __forceinline__ void mma_tf32(float* d, const uint32_t* a, const uint32_t* b) {
    asm volatile(
        "mma.sync.aligned.m16n8k8.row.col.f32.tf32.tf32.f32 "
        "{%0,%1,%2,%3}, {%4,%5,%6,%7}, {%8,%9}, {%0,%1,%2,%3};"
        : "+f"(d[0]), "+f"(d[1]), "+f"(d[2]), "+f"(d[3])
        : "r"(a[0]), "r"(a[1]), "r"(a[2]), "r"(a[3]), "r"(b[0]), "r"(b[1]));
}

// ---------------------------------------------------------------------------
// TF32 tensor-core GEMM with 3xTF32 split (fp32-grade accuracy).
// C[M,128] = A[M,K] @ W[K,128] (+bias) (+Cadd) (+relu) (row0 mask)
// CTA tile 128x128, BK=16, 256 threads = 8 warps (4M x 2N), warp tile 32x64.
// flags: 1=add bias[col], 2=add Cadd[row,col], 4=relu, 8=zero global row 0
// ---------------------------------------------------------------------------
#define BK 16
#define APAD 20     // A row pitch (floats): 20 % 32 cycles banks conflict-free
#define BPAD 136    // B row pitch: 136 % 32 == 8 -> conflict-free b-frag reads

__global__ void __launch_bounds__(256) gemm_tf32_kernel(
    const float* __restrict__ A, int lda, int M, int K,
    const float* __restrict__ W,
    const float* __restrict__ bias,
    const float* __restrict__ Cadd,
    float* __restrict__ C, int flags)
{
    __shared__ float Ah[128][APAD];
    __shared__ float Al[128][APAD];
    __shared__ float Bh[BK][BPAD];
    __shared__ float Bl[BK][BPAD];

    const int tid  = threadIdx.x;
    const int lane = tid & 31;
    const int warp = tid >> 5;
    const int wm   = warp & 3;        // 0..3 -> M offset wm*32
    const int wn   = warp >> 2;       // 0..1 -> N offset wn*64
    const int g    = lane >> 2;       // group id 0..7
    const int t    = lane & 3;        // thread-in-group 0..3
    const int r0   = blockIdx.x * 128;

    float acc[2][8][4];
#pragma unroll
    for (int mt = 0; mt < 2; mt++)
#pragma unroll
        for (int nt = 0; nt < 8; nt++)
#pragma unroll
            for (int i = 0; i < 4; i++) acc[mt][nt][i] = 0.0f;

    // A-tile loader mapping: 128 rows x 16 k = 2048 floats, 8/thread (2 float4)
    const int ac4  = tid & 3;         // which float4 along K
    const int arow = tid >> 2;        // 0..63 (rows arow, arow+64)
    // B-tile loader mapping: 16 k x 128 n = 2048 floats
    const int bkr  = tid >> 5;        // 0..7 (rows bkr, bkr+8)
    const int bc4  = tid & 31;        // float4 along n

    for (int kt = 0; kt < K; kt += BK) {
        // ---- stage A (split into tf32 hi/lo)
#pragma unroll
        for (int rr = 0; rr < 2; rr++) {
            int r = arow + rr * 64;
            int grow = r0 + r;
            float4 v = make_float4(0.f, 0.f, 0.f, 0.f);
            if (grow < M)
                v = *(const float4*)(A + (size_t)grow * lda + kt + ac4 * 4);
            const float vv[4] = {v.x, v.y, v.z, v.w};
#pragma unroll
            for (int j = 0; j < 4; j++) {
                uint32_t hb = f2tf32(vv[j]);
                float hf = __uint_as_float(hb);
                uint32_t lb = f2tf32(vv[j] - hf);
                Ah[r][ac4 * 4 + j] = hf;
                Al[r][ac4 * 4 + j] = __uint_as_float(lb);
            }
        }
        // ---- stage B (split into tf32 hi/lo)
#pragma unroll
        for (int rr = 0; rr < 2; rr++) {
            int kr = bkr + rr * 8;
            float4 v = *(const float4*)(W + (size_t)(kt + kr) * HD + bc4 * 4);
            const float vv[4] = {v.x, v.y, v.z, v.w};
#pragma unroll
            for (int j = 0; j < 4; j++) {
                uint32_t hb = f2tf32(vv[j]);
                float hf = __uint_as_float(hb);
                uint32_t lb = f2tf32(vv[j] - hf);
                Bh[kr][bc4 * 4 + j] = hf;
                Bl[kr][bc4 * 4 + j] = __uint_as_float(lb);
            }
        }
        __syncthreads();

#pragma unroll
        for (int ks = 0; ks < BK / 8; ks++) {
            const int k0 = ks * 8;
            // A fragments: rows wm*32 + mt*16 + {g, g+8}, cols k0 + {t, t+4}
            uint32_t aH[2][4], aL[2][4];
#pragma unroll
            for (int mt = 0; mt < 2; mt++) {
                int m0 = wm * 32 + mt * 16;
                aH[mt][0] = __float_as_uint(Ah[m0 + g][k0 + t]);
                aH[mt][1] = __float_as_uint(Ah[m0 + g + 8][k0 + t]);
                aH[mt][2] = __float_as_uint(Ah[m0 + g][k0 + t + 4]);
                aH[mt][3] = __float_as_uint(Ah[m0 + g + 8][k0 + t + 4]);
                aL[mt][0] = __float_as_uint(Al[m0 + g][k0 + t]);
                aL[mt][1] = __float_as_uint(Al[m0 + g + 8][k0 + t]);
                aL[mt][2] = __float_as_uint(Al[m0 + g][k0 + t + 4]);
                aL[mt][3] = __float_as_uint(Al[m0 + g + 8][k0 + t + 4]);
            }
            // B fragments: k rows k0 + {t, t+4}, col n0 + g
            uint32_t bH[8][2], bL[8][2];
#pragma unroll
            for (int nt = 0; nt < 8; nt++) {
                int n = wn * 64 + nt * 8 + g;
                bH[nt][0] = __float_as_uint(Bh[k0 + t][n]);
                bH[nt][1] = __float_as_uint(Bh[k0 + t + 4][n]);
                bL[nt][0] = __float_as_uint(Bl[k0 + t][n]);
                bL[nt][1] = __float_as_uint(Bl[k0 + t + 4][n]);
            }
#pragma unroll
            for (int mt = 0; mt < 2; mt++)
#pragma unroll
                for (int nt = 0; nt < 8; nt++) {
                    mma_tf32(acc[mt][nt], aL[mt], bH[nt]);
                    mma_tf32(acc[mt][nt], aH[mt], bL[nt]);
                    mma_tf32(acc[mt][nt], aH[mt], bH[nt]);
                }
        }
        __syncthreads();
    }

    // ---- epilogue
#pragma unroll
    for (int mt = 0; mt < 2; mt++) {
#pragma unroll
        for (int i = 0; i < 2; i++) {
            int row = r0 + wm * 32 + mt * 16 + g + i * 8;
            if (row >= M) continue;
#pragma unroll
            for (int nt = 0; nt < 8; nt++) {
                int col = wn * 64 + nt * 8 + 2 * t;
                float v0 = acc[mt][nt][i * 2 + 0];
                float v1 = acc[mt][nt][i * 2 + 1];
                if (flags & 1) { v0 += bias[col]; v1 += bias[col + 1]; }
                if (flags & 2) {
                    float2 ca = *(const float2*)(Cadd + (size_t)row * HD + col);
                    v0 += ca.x; v1 += ca.y;
                }
                if (flags & 4) { v0 = fmaxf(v0, 0.0f); v1 = fmaxf(v1, 0.0f); }
                if ((flags & 8) && row == 0) { v0 = 0.0f; v1 = 0.0f; }
                *(float2*)(C + (size_t)row * HD + col) = make_float2(v0, v1);
            }
        }
    }
}

// ---------------------------------------------------------------------------
// init_h: h = sigmoid(Z1) * tanh(H1), row 0 zeroed. (depth-step 1 with h=0)
// ---------------------------------------------------------------------------
__global__ void init_h_kernel(int total4, const float* __restrict__ Z1,
                              const float* __restrict__ H1,
                              float* __restrict__ h)
{
    int i = blockIdx.x * blockDim.x + threadIdx.x;
    if (i >= total4) return;
    float4 z = ((const float4*)Z1)[i];
    float4 p = ((const float4*)H1)[i];
    float4 o;
    o.x = sigm(z.x) * tanhf(p.x);
    o.y = sigm(z.y) * tanhf(p.y);
    o.z = sigm(z.z) * tanhf(p.z);
    o.w = sigm(z.w) * tanhf(p.w);
    if (i < HD / 4) { o.x = o.y = o.z = o.w = 0.0f; }
    ((float4*)h)[i] = o;
}

// ---------------------------------------------------------------------------
// msg_gather: one warp per message.
// ---------------------------------------------------------------------------
__global__ void __launch_bounds__(256) msg_gather_kernel(
    const int* __restrict__ bgraph, int M,
    const float* __restrict__ h, const float* __restrict__ HU,
    const float* __restrict__ R1,
    float* __restrict__ SumH, float* __restrict__ SumG)
{
    int warp = (blockIdx.x * blockDim.x + threadIdx.x) >> 5;
    if (warp >= M) return;
    int lane = threadIdx.x & 31;
    int d = lane * 4;

    float4 r1 = *(const float4*)(R1 + (size_t)warp * HD + d);
    float4 sh = make_float4(0.f, 0.f, 0.f, 0.f);
    float4 sg = make_float4(0.f, 0.f, 0.f, 0.f);

#pragma unroll
    for (int k = 0; k < KNB; k++) {
        int b = __ldg(bgraph + (size_t)warp * KNB + k);
        float4 hv = *(const float4*)(h  + (size_t)b * HD + d);
        float4 hu = *(const float4*)(HU + (size_t)b * HD + d);
        sh.x += hv.x; sh.y += hv.y; sh.z += hv.z; sh.w += hv.w;
        sg.x += sigm(r1.x + hu.x) * hv.x;
        sg.y += sigm(r1.y + hu.y) * hv.y;
        sg.z += sigm(r1.z + hu.z) * hv.z;
        sg.w += sigm(r1.w + hu.w) * hv.w;
    }
    *(float4*)(SumH + (size_t)warp * HD + d) = sh;
    *(float4*)(SumG + (size_t)warp * HD + d) = sg;
}

// ---------------------------------------------------------------------------
// update_h
// ---------------------------------------------------------------------------
__global__ void update_h_kernel(int total4,
                                const float* __restrict__ Z1,
                                const float* __restrict__ Zlin,
                                const float* __restrict__ H1,
                                const float* __restrict__ Hlin,
                                const float* __restrict__ SumH,
                                float* __restrict__ h)
{
    int i = blockIdx.x * blockDim.x + threadIdx.x;
    if (i >= total4) return;
    float4 z1 = ((const float4*)Z1)[i];
    float4 zl = ((const float4*)Zlin)[i];
    float4 h1 = ((const float4*)H1)[i];
    float4 hl = ((const float4*)Hlin)[i];
    float4 s  = ((const float4*)SumH)[i];
    float4 o;
    { float z = sigm(z1.x + zl.x); float p = tanhf(h1.x + hl.x); o.x = (1.0f - z) * s.x + z * p; }
    { float z = sigm(z1.y + zl.y); float p = tanhf(h1.y + hl.y); o.y = (1.0f - z) * s.y + z * p; }
    { float z = sigm(z1.z + zl.z); float p = tanhf(h1.z + hl.z); o.z = (1.0f - z) * s.z + z * p; }
    { float z = sigm(z1.w + zl.w); float p = tanhf(h1.w + hl.w); o.w = (1.0f - z) * s.w + z * p; }
    if (i < HD / 4) { o.x = o.y = o.z = o.w = 0.0f; }
    ((float4*)h)[i] = o;
}

// ---------------------------------------------------------------------------
// node_gather
// ---------------------------------------------------------------------------
__global__ void __launch_bounds__(256) node_gather_kernel(
    const int* __restrict__ agraph, int N,
    const float* __restrict__ h, float* __restrict__ NEI)
{
    int warp = (blockIdx.x * blockDim.x + threadIdx.x) >> 5;
    if (warp >= N) return;
    int lane = threadIdx.x & 31;
    int d = lane * 4;
    float4 s = make_float4(0.f, 0.f, 0.f, 0.f);
#pragma unroll
    for (int k = 0; k < KNB; k++) {
        int b = __ldg(agraph + (size_t)warp * KNB + k);
        float4 hv = *(const float4*)(h + (size_t)b * HD + d);
        s.x += hv.x; s.y += hv.y; s.z += hv.z; s.w += hv.w;
    }
    *(float4*)(NEI + (size_t)warp * HD + d) = s;
}

// ---------------------------------------------------------------------------
// Host-side orchestration
// ---------------------------------------------------------------------------
extern "C" void kernel_launch(void* const* d_in, const int* in_sizes, int n_in,
                              void* d_out, int out_size)
{
    const float* fnode  = (const float*)d_in[0];
    const float* fmess  = (const float*)d_in[1];
    const int*   agraph = (const int*)  d_in[2];
    const int*   bgraph = (const int*)  d_in[3];
    const float* W_z_w  = (const float*)d_in[4];   // [160+128, 128]
    const float* W_z_b  = (const float*)d_in[5];
    const float* W_r_w  = (const float*)d_in[6];   // [160, 128]
    const float* U_r_w  = (const float*)d_in[7];   // [128, 128]
    const float* U_r_b  = (const float*)d_in[8];
    const float* W_h_w  = (const float*)d_in[9];   // [160+128, 128]
    const float* W_h_b  = (const float*)d_in[10];
    const float* W_o_w  = (const float*)d_in[11];  // [128+128, 128]
    const float* W_o_b  = (const float*)d_in[12];
    float* out = (float*)d_out;

    const int N = in_sizes[0] / HD;   // nodes
    const int M = in_sizes[1] / FM;   // messages

    float* S = nullptr;
    cudaGetSymbolAddress((void**)&S, g_scratch);

    float* Z1   = S + 0 * MH;
    float* H1   = S + 1 * MH;
    float* R1   = S + 2 * MH;
    float* h    = S + 3 * MH;
    float* HU   = S + 4 * MH;
    float* SumH = S + 5 * MH;
    float* SumG = S + 6 * MH;
    float* Zlin = S + 7 * MH;
    float* Hlin = S + 8 * MH;
    float* NEI  = S + 9 * MH;
    float* T    = S + 9 * MH + NH;

    const int gemmBlocksM = (M + 127) / 128;
    const int gemmBlocksN = (N + 127) / 128;
    const dim3 tb(256);

    const int total4M = (int)((size_t)M * HD / 4);
    const int ewBlocksM = (total4M + 255) / 256;
    const int gatherBlocksM = (M + 7) / 8;
    const int gatherBlocksN = (N + 7) / 8;

    // ---- loop-invariant precompute
    gemm_tf32_kernel<<<gemmBlocksM, tb>>>(fmess, FM, M, FM, W_z_w, W_z_b, nullptr, Z1, 1);
    gemm_tf32_kernel<<<gemmBlocksM, tb>>>(fmess, FM, M, FM, W_h_w, W_h_b, nullptr, H1, 1);
    gemm_tf32_kernel<<<gemmBlocksM, tb>>>(fmess, FM, M, FM, W_r_w, U_r_b, nullptr, R1, 1);

    // ---- depth step 1 (h = 0): pure elementwise
    init_h_kernel<<<ewBlocksM, tb>>>(total4M, Z1, H1, h);

    // ---- depth steps 2..5
    const float* Wz_h = W_z_w + (size_t)FM * HD;
    const float* Wh_h = W_h_w + (size_t)FM * HD;
    for (int it = 0; it < 4; it++) {
        gemm_tf32_kernel<<<gemmBlocksM, tb>>>(h, HD, M, HD, U_r_w, nullptr, nullptr, HU, 0);
        msg_gather_kernel<<<gatherBlocksM, tb>>>(bgraph, M, h, HU, R1, SumH, SumG);
        gemm_tf32_kernel<<<gemmBlocksM, tb>>>(SumH, HD, M, HD, Wz_h, nullptr, nullptr, Zlin, 0);
        gemm_tf32_kernel<<<gemmBlocksM, tb>>>(SumG, HD, M, HD, Wh_h, nullptr, nullptr, Hlin, 0);
        update_h_kernel<<<ewBlocksM, tb>>>(total4M, Z1, Zlin, H1, Hlin, SumH, h);
    }

    // ---- readout
    node_gather_kernel<<<gatherBlocksN, tb>>>(agraph, N, h, NEI);
    gemm_tf32_kernel<<<gemmBlocksN, tb>>>(fnode, HD, N, HD, W_o_w, W_o_b, nullptr, T, 1);
    const float* Wo_h = W_o_w + (size_t)HD * HD;
    gemm_tf32_kernel<<<gemmBlocksN, tb>>>(NEI, HD, N, HD, Wo_h, nullptr, T, out, 2 | 4 | 8);
}